// round 16
// baseline (speedup 1.0000x reference)
#include <cuda_runtime.h>
#include <cuda_bf16.h>
#include <cstdint>
#include <cmath>

// Problem constants
#define BATCH   2
#define LSEQ    2048
#define DMODEL  1024
#define DINNER  2048
#define DSTATE  16
#define NROWS   (BATCH*LSEQ)          // 4096
#define XZW     (2*DINNER)            // 4096
#define KSPLIT  16                    // bcd split-K factor

// ---------------- scratch (static device arrays; no allocation) ------------
__device__ float g_xz   [(size_t)NROWS * XZW];     // x@W_in (x_|z)
__device__ float g_xs   [(size_t)NROWS * DINNER];  // silu(conv(x_))
__device__ float g_Bc   [(size_t)NROWS * DSTATE];
__device__ float g_Cc   [(size_t)NROWS * DSTATE];
__device__ float g_delta[NROWS];
__device__ float g_part [(size_t)KSPLIT * NROWS * 36];   // bcd split-K partials

// bf16 split operands for tensor-core GEMMs (aligned for 16B cp.async)
__device__ __align__(128) __nv_bfloat16 g_xa_h[(size_t)NROWS * DMODEL];
__device__ __align__(128) __nv_bfloat16 g_xa_l[(size_t)NROWS * DMODEL];
__device__ __align__(128) __nv_bfloat16 g_w1_h[(size_t)XZW * DMODEL];     // W_in^T  [4096,1024]
__device__ __align__(128) __nv_bfloat16 g_w1_l[(size_t)XZW * DMODEL];
__device__ __align__(128) __nv_bfloat16 g_ya_h[(size_t)NROWS * DINNER];
__device__ __align__(128) __nv_bfloat16 g_ya_l[(size_t)NROWS * DINNER];
__device__ __align__(128) __nv_bfloat16 g_w2_h[(size_t)DMODEL * DINNER];  // W_out^T [1024,2048]
__device__ __align__(128) __nv_bfloat16 g_w2_l[(size_t)DMODEL * DINNER];

// ============================ PTX helpers (sm_100-safe) =====================
__device__ __forceinline__ uint32_t smem_u32(const void* p) {
    uint32_t a;
    asm("{ .reg .u64 t; cvta.to.shared.u64 t, %1; cvt.u32.u64 %0, t; }" : "=r"(a) : "l"(p));
    return a;
}
__device__ __forceinline__ void cp16(uint32_t dst, const void* src) {
    asm volatile("cp.async.cg.shared.global [%0], [%1], 16;" :: "r"(dst), "l"(src));
}
__device__ __forceinline__ void cp_commit() {
    asm volatile("cp.async.commit_group;" ::: "memory");
}
__device__ __forceinline__ void ldsm4(uint32_t* r, uint32_t a) {
    asm volatile("ldmatrix.sync.aligned.m8n8.x4.shared.b16 {%0,%1,%2,%3}, [%4];"
        : "=r"(r[0]), "=r"(r[1]), "=r"(r[2]), "=r"(r[3]) : "r"(a));
}
__device__ __forceinline__ void mma16816(float* d, const uint32_t* a, uint32_t b0, uint32_t b1) {
    asm volatile("mma.sync.aligned.m16n8k16.row.col.f32.bf16.bf16.f32 "
        "{%0,%1,%2,%3},{%4,%5,%6,%7},{%8,%9},{%0,%1,%2,%3};"
        : "+f"(d[0]), "+f"(d[1]), "+f"(d[2]), "+f"(d[3])
        : "r"(a[0]), "r"(a[1]), "r"(a[2]), "r"(a[3]), "r"(b0), "r"(b1));
}
__device__ __forceinline__ float silu_f(float v) {
    return v / (1.f + __expf(-v));
}

// ============================================================================
// Tensor-core GEMM (R12 validated config, unchanged):  C = A @ B^T.
// CTA tile 128x64, K chunks of 64, 2-stage cp.async (96KB -> 2 CTAs/SM),
// 256 threads, warp tile 32x32, 3-term bf16 split accumulation.
// ============================================================================
#define STAGE_BYTES 49152u   // Ah 16K | Al 16K | Bh 8K | Bl 8K

__global__ __launch_bounds__(256, 2) void gemm_mma(
    const __nv_bfloat16* __restrict__ Ah, const __nv_bfloat16* __restrict__ Al,
    const __nv_bfloat16* __restrict__ Bh, const __nv_bfloat16* __restrict__ Bl,
    float* __restrict__ C, int M, int N, int K)
{
    extern __shared__ char smem[];
    const uint32_t sb = smem_u32(smem);

    const int tid  = threadIdx.x;
    const int lane = tid & 31, wid = tid >> 5;
    const int wm   = wid >> 1, wn = wid & 1;
    const int m0   = blockIdx.y * 128, n0 = blockIdx.x * 64;
    const int NC   = K >> 6;

    const int lrow0 = tid >> 3;
    const int lseg  = tid & 7;
    const int lr    = lane & 15;
    const int lc    = lane >> 4;

    float acc[2][4][4];
#pragma unroll
    for (int i = 0; i < 2; ++i)
#pragma unroll
        for (int j = 0; j < 4; ++j)
#pragma unroll
            for (int q = 0; q < 4; ++q) acc[i][j][q] = 0.f;

    auto LOAD = [&](int c) {
        const int kc = c << 6;
        const uint32_t base = sb + (uint32_t)(c & 1) * STAGE_BYTES;
#pragma unroll
        for (int i = 0; i < 4; ++i) {
            int row = lrow0 + i * 32;
            uint32_t ro = (uint32_t)row * 128u + (uint32_t)((lseg ^ (row & 7)) << 4);
            cp16(base + ro,          Ah + (size_t)(m0 + row) * K + kc + lseg * 8);
            cp16(base + 16384u + ro, Al + (size_t)(m0 + row) * K + kc + lseg * 8);
        }
#pragma unroll
        for (int i = 0; i < 2; ++i) {
            int row = lrow0 + i * 32;
            uint32_t ro = (uint32_t)row * 128u + (uint32_t)((lseg ^ (row & 7)) << 4);
            cp16(base + 32768u + ro, Bh + (size_t)(n0 + row) * K + kc + lseg * 8);
            cp16(base + 40960u + ro, Bl + (size_t)(n0 + row) * K + kc + lseg * 8);
        }
        cp_commit();
    };

    LOAD(0);
    if (NC > 1) LOAD(1);

    for (int c = 0; c < NC; ++c) {
        if (c + 1 < NC) asm volatile("cp.async.wait_group 1;" ::: "memory");
        else            asm volatile("cp.async.wait_group 0;" ::: "memory");
        __syncthreads();

        const uint32_t ab = sb + (uint32_t)(c & 1) * STAGE_BYTES;
        const uint32_t bb = ab + 32768u;

#pragma unroll
        for (int ks = 0; ks < 4; ++ks) {
            uint32_t ah[2][4], al[2][4], bh[2][4], bl[2][4];
#pragma unroll
            for (int am = 0; am < 2; ++am) {
                int row = wm * 32 + am * 16 + lr;
                uint32_t c16 = (uint32_t)((ks * 2 + lc) ^ (row & 7));
                uint32_t off = (uint32_t)row * 128u + (c16 << 4);
                ldsm4(ah[am], ab + off);
                ldsm4(al[am], ab + 16384u + off);
            }
#pragma unroll
            for (int nb = 0; nb < 2; ++nb) {
                int row = wn * 32 + nb * 16 + lr;
                uint32_t c16 = (uint32_t)((ks * 2 + lc) ^ (row & 7));
                uint32_t off = (uint32_t)row * 128u + (c16 << 4);
                ldsm4(bh[nb], bb + off);
                ldsm4(bl[nb], bb + 8192u + off);
            }
#pragma unroll
            for (int am = 0; am < 2; ++am)
#pragma unroll
                for (int nb = 0; nb < 2; ++nb)
#pragma unroll
                    for (int h2 = 0; h2 < 2; ++h2)
                        mma16816(acc[am][nb * 2 + h2], ah[am], bh[nb][h2], bh[nb][h2 + 2]);
#pragma unroll
            for (int am = 0; am < 2; ++am)
#pragma unroll
                for (int nb = 0; nb < 2; ++nb)
#pragma unroll
                    for (int h2 = 0; h2 < 2; ++h2)
                        mma16816(acc[am][nb * 2 + h2], ah[am], bl[nb][h2], bl[nb][h2 + 2]);
#pragma unroll
            for (int am = 0; am < 2; ++am)
#pragma unroll
                for (int nb = 0; nb < 2; ++nb)
#pragma unroll
                    for (int h2 = 0; h2 < 2; ++h2)
                        mma16816(acc[am][nb * 2 + h2], al[am], bh[nb][h2], bh[nb][h2 + 2]);
        }
        __syncthreads();
        if (c + 2 < NC) LOAD(c + 2);
    }

    const int er = lane >> 2, ec = (lane & 3) * 2;
#pragma unroll
    for (int am = 0; am < 2; ++am) {
        int row = m0 + wm * 32 + am * 16 + er;
#pragma unroll
        for (int na = 0; na < 4; ++na) {
            int col = n0 + wn * 32 + na * 8 + ec;
            float* d = acc[am][na];
            *reinterpret_cast<float2*>(C + (size_t)row * N + col)       = make_float2(d[0], d[1]);
            *reinterpret_cast<float2*>(C + (size_t)(row + 8) * N + col) = make_float2(d[2], d[3]);
        }
    }
}

// ============================================================================
// Merged prep: tr_split(W_in) | tr_split(W_out) | split(x) in one launch
// ============================================================================
__device__ __forceinline__ void tr_split_body(
    float (*t)[33], const float* __restrict__ W,
    __nv_bfloat16* __restrict__ hi, __nv_bfloat16* __restrict__ lo,
    int K, int N, int k0, int n0)
{
    const int tx = threadIdx.x & 31, ty = threadIdx.x >> 5;
#pragma unroll
    for (int i = 0; i < 4; ++i)
        t[ty + i * 8][tx] = W[(size_t)(k0 + ty + i * 8) * N + n0 + tx];
    __syncthreads();
#pragma unroll
    for (int i = 0; i < 4; ++i) {
        int n = n0 + ty + i * 8;
        float v = t[tx][ty + i * 8];
        __nv_bfloat16 h = __float2bfloat16(v);
        hi[(size_t)n * K + k0 + tx] = h;
        lo[(size_t)n * K + k0 + tx] = __float2bfloat16(v - __bfloat162float(h));
    }
}

__global__ __launch_bounds__(256) void prep_k(
    const float* __restrict__ W_in,  __nv_bfloat16* __restrict__ w1h, __nv_bfloat16* __restrict__ w1l,
    const float* __restrict__ W_out, __nv_bfloat16* __restrict__ w2h, __nv_bfloat16* __restrict__ w2l,
    const float* __restrict__ x,     __nv_bfloat16* __restrict__ xh,  __nv_bfloat16* __restrict__ xl)
{
    __shared__ float t[32][33];
    int b = blockIdx.x;
    if (b < 4096) {
        int bx = b & 127, by = b >> 7;
        tr_split_body(t, W_in, w1h, w1l, DMODEL, XZW, by * 32, bx * 32);
    } else if (b < 6144) {
        b -= 4096;
        int bx = b & 31, by = b >> 5;
        tr_split_body(t, W_out, w2h, w2l, DINNER, DMODEL, by * 32, bx * 32);
    } else {
        b -= 6144;
        int i = b * 256 + threadIdx.x;
        float4 v = reinterpret_cast<const float4*>(x)[i];
        __nv_bfloat16 h0 = __float2bfloat16(v.x), h1 = __float2bfloat16(v.y);
        __nv_bfloat16 h2 = __float2bfloat16(v.z), h3 = __float2bfloat16(v.w);
        reinterpret_cast<__nv_bfloat162*>(xh)[2 * i]     = __halves2bfloat162(h0, h1);
        reinterpret_cast<__nv_bfloat162*>(xh)[2 * i + 1] = __halves2bfloat162(h2, h3);
        __nv_bfloat16 l0 = __float2bfloat16(v.x - __bfloat162float(h0));
        __nv_bfloat16 l1 = __float2bfloat16(v.y - __bfloat162float(h1));
        __nv_bfloat16 l2 = __float2bfloat16(v.z - __bfloat162float(h2));
        __nv_bfloat16 l3 = __float2bfloat16(v.w - __bfloat162float(h3));
        reinterpret_cast<__nv_bfloat162*>(xl)[2 * i]     = __halves2bfloat162(l0, l1);
        reinterpret_cast<__nv_bfloat162*>(xl)[2 * i + 1] = __halves2bfloat162(l2, l3);
    }
}

// ============================================================================
// Depthwise causal conv (k=4) + bias + SiLU.  4 consecutive l per thread.
// ============================================================================
__global__ __launch_bounds__(256) void conv_silu_k(
    const float* __restrict__ xz, const float* __restrict__ cw,
    const float* __restrict__ cb, float* __restrict__ xs)
{
    int idx  = blockIdx.x * 256 + threadIdx.x;
    int d4   = (idx & (DINNER / 4 - 1)) << 2;
    int rb   = idx >> 9;
    int r0   = rb << 2;
    int l0   = r0 & (LSEQ - 1);

    float4 bias = *reinterpret_cast<const float4*>(cb + d4);
    float4 w0 = reinterpret_cast<const float4*>(cw)[d4 + 0];
    float4 w1 = reinterpret_cast<const float4*>(cw)[d4 + 1];
    float4 w2 = reinterpret_cast<const float4*>(cw)[d4 + 2];
    float4 w3 = reinterpret_cast<const float4*>(cw)[d4 + 3];

    float4 v[7];
#pragma unroll
    for (int j = 0; j < 7; ++j) {
        int l = l0 - 3 + j;
        v[j] = (l >= 0)
             ? *reinterpret_cast<const float4*>(xz + (size_t)(r0 - 3 + j) * XZW + d4)
             : make_float4(0.f, 0.f, 0.f, 0.f);
    }
#pragma unroll
    for (int i = 0; i < 4; ++i) {
        float4 acc = bias;
#pragma unroll
        for (int k = 0; k < 4; ++k) {
            float4 xv = v[i + k];
            acc.x = fmaf((&w0.x)[k], xv.x, acc.x);
            acc.y = fmaf((&w1.x)[k], xv.y, acc.y);
            acc.z = fmaf((&w2.x)[k], xv.z, acc.z);
            acc.w = fmaf((&w3.x)[k], xv.w, acc.w);
        }
        acc.x = silu_f(acc.x); acc.y = silu_f(acc.y);
        acc.z = silu_f(acc.z); acc.w = silu_f(acc.w);
        *reinterpret_cast<float4*>(xs + (size_t)(r0 + i) * DINNER + d4) = acc;
    }
}

// ============================================================================
// bcd split-K (KSPLIT=16): 4 chunk-iters per CTA, 2048 CTAs.
// ============================================================================
__global__ __launch_bounds__(256) void bcd_k(
    const float* __restrict__ xs, const float* __restrict__ Wx,
    float* __restrict__ part)
{
    __shared__ float sX[32 * 33];
    __shared__ float sW[32 * 36];

    const int tid  = threadIdx.x;
    const int row0 = blockIdx.x * 32;
    const int ks   = blockIdx.y;
    const int kb   = ks * (DINNER / KSPLIT);
    const int row  = tid & 31;
    const int g    = tid >> 5;

    float acc0 = 0.f, acc1 = 0.f, acc2 = 0.f, acc3 = 0.f, accd = 0.f;

    for (int kc = kb; kc < kb + DINNER / KSPLIT; kc += 32) {
        for (int e = tid; e < 32 * 36; e += 256) {
            int k = e / 36, n = e - k * 36;
            sW[e] = (n < 33) ? Wx[(size_t)(kc + k) * 33 + n] : 0.f;
        }
        {
            int r = tid >> 3, c4 = tid & 7;
            float4 v = *(const float4*)(xs + (size_t)(row0 + r) * DINNER + kc + c4 * 4);
            int kk = c4 * 4;
            sX[(kk + 0) * 33 + r] = v.x;
            sX[(kk + 1) * 33 + r] = v.y;
            sX[(kk + 2) * 33 + r] = v.z;
            sX[(kk + 3) * 33 + r] = v.w;
        }
        __syncthreads();
#pragma unroll 8
        for (int k = 0; k < 32; ++k) {
            float  xv = sX[k * 33 + row];
            float4 wv = *(const float4*)(&sW[k * 36 + g * 4]);
            acc0 = fmaf(xv, wv.x, acc0);
            acc1 = fmaf(xv, wv.y, acc1);
            acc2 = fmaf(xv, wv.z, acc2);
            acc3 = fmaf(xv, wv.w, acc3);
            if (g == 0) accd = fmaf(xv, sW[k * 36 + 32], accd);
        }
        __syncthreads();
    }

    float* dst = part + ((size_t)ks * NROWS + row0 + row) * 36;
    float a[4] = {acc0, acc1, acc2, acc3};
#pragma unroll
    for (int j = 0; j < 4; ++j) dst[g * 4 + j] = a[j];
    if (g == 0) dst[32] = accd;
}

// Reduce the KSPLIT partials -> gB, gC, gdelta (fixed order: deterministic)
__global__ __launch_bounds__(256) void bcd_red(
    const float* __restrict__ part,
    float* __restrict__ gB, float* __restrict__ gC, float* __restrict__ gdelta)
{
    int idx = blockIdx.x * 256 + threadIdx.x;      // < 4096*33
    if (idx >= NROWS * 33) return;
    int row = idx / 33, n = idx - row * 33;
    float s = 0.f;
#pragma unroll
    for (int k = 0; k < KSPLIT; ++k)
        s += part[((size_t)k * NROWS + row) * 36 + n];
    if (n < 16)       gB[(size_t)row * 16 + n]        = s;
    else if (n < 32)  gC[(size_t)row * 16 + (n - 16)] = s;
    else              gdelta[row]                     = s;
}

// ============================================================================
// Selective scan v5: shfl pre-reduction (16 -> 4 partials, off the h-path),
// (dt*x, x) packed staging, 4x smaller sp region, 1 LDS.128 per output.
// smem (floats): sBC 2048 | sdx 2048 | sz 1024 | sp 64*68=4352 | sDp 16
// ============================================================================
#define SCAN_SMEM_FLOATS (2048 + 2048 + 1024 + 64*68 + 16)

__global__ __launch_bounds__(256) void scan_k(
    const float* __restrict__ gdelta, const float* __restrict__ w_dt,
    const float* __restrict__ b_dt,
    const float* __restrict__ gxs,  const float* __restrict__ gxz,
    const float* __restrict__ gB,   const float* __restrict__ gC,
    const float* __restrict__ A_log, const float* __restrict__ Dp,
    __nv_bfloat16* __restrict__ yh, __nv_bfloat16* __restrict__ yl)
{
    extern __shared__ float sm[];
    float2* sBC = (float2*)sm;             // [l*16+n] -> (B, C)
    float2* sdx = (float2*)(sm + 2048);    // [l*16+d] -> (dt*x, x)
    float*  sz  = sm + 4096;
    float*  sp  = sm + 5120;               // [l*68 + chain*4 + q], q<4
    float*  sDp = sm + 5120 + 64*68;

    const int tid  = threadIdx.x;
    const int lane = tid & 31;
    const int w    = tid >> 5;
    const int cidx = 2 * w + (lane >> 4);
    const int n    = lane & 15;
    const int b    = blockIdx.x >> 7;
    const int d0   = (blockIdx.x & 127) * 16;
    const int d    = d0 + cidx;

    if (tid < 16) sDp[tid] = Dp[d0 + tid];

    const float A = -expf(A_log[d * DSTATE + n]);
    float h = 0.f;
    const int spb = cidx * 4 + (n & 3);   // slot if this lane stores

    const int sl = tid >> 2;
    const int c0 = (tid & 3) << 2;
    const float4 wd = *reinterpret_cast<const float4*>(w_dt + d0 + c0);
    const float4 bd = *reinterpret_cast<const float4*>(b_dt + d0 + c0);

    for (int t0 = 0; t0 < LSEQ; t0 += 64) {
        // ---- stage tiles ----
        {
            size_t base_bc = (size_t)(b * LSEQ + t0) * DSTATE;
            float4 bv = ((const float4*)(gB + base_bc))[tid];
            float4 cv = ((const float4*)(gC + base_bc))[tid];
            float2* dst = sBC + tid * 4;
            dst[0] = make_float2(bv.x, cv.x);
            dst[1] = make_float2(bv.y, cv.y);
            dst[2] = make_float2(bv.z, cv.z);
            dst[3] = make_float2(bv.w, cv.w);

            size_t grow = (size_t)(b * LSEQ + t0 + sl);
            float  del  = gdelta[grow];
            float4 xv   = *reinterpret_cast<const float4*>(gxs + grow * DINNER + d0 + c0);
            float4 zv   = *reinterpret_cast<const float4*>(gxz + grow * XZW + DINNER + d0 + c0);

            float sp0 = fmaf(del, wd.x, bd.x);
            float sp1 = fmaf(del, wd.y, bd.y);
            float sp2 = fmaf(del, wd.z, bd.z);
            float sp3 = fmaf(del, wd.w, bd.w);
            sp0 = (sp0 > 30.f) ? sp0 : log1pf(__expf(sp0));
            sp1 = (sp1 > 30.f) ? sp1 : log1pf(__expf(sp1));
            sp2 = (sp2 > 30.f) ? sp2 : log1pf(__expf(sp2));
            sp3 = (sp3 > 30.f) ? sp3 : log1pf(__expf(sp3));

            float2* dsx = sdx + sl * 16 + c0;
            dsx[0] = make_float2(sp0 * xv.x, xv.x);
            dsx[1] = make_float2(sp1 * xv.y, xv.y);
            dsx[2] = make_float2(sp2 * xv.z, xv.z);
            dsx[3] = make_float2(sp3 * xv.w, xv.w);
            *reinterpret_cast<float4*>(sz + sl * 16 + c0) = zv;
        }
        __syncthreads();

        // ---- 64 sequential steps: recurrence + shfl pre-reduce ----
#pragma unroll 4
        for (int l = 0; l < 64; ++l) {
            float2 dx = sdx[l * 16 + cidx];   // (dt*x, x); dt via ratio not needed:
            float2 bc = sBC[l * 16 + n];      // (B, C)
            // a = exp(dt*A): dt = dx.x/dx.y unstable; keep dt separately? ->
            // dt*A = (dt)*A; we stored dt*x, so recompute dt*A needs dt.
            // Instead: a = exp(dtA) where dtA staged? No: use dx.y-independent:
            // NOTE: we still need dt alone for 'a'. Store dt in sz? sz holds z.
            // Solution: bc-path unchanged; dt*A from dtx/x is unsafe (x may be 0).
            // -> We staged (dt*x, dt) instead; x recovered at epilogue via gxs?
            // See staging: dsx = (dt*x, x). For 'a' we need dt: dt = ?
            // This comment documents the hazard; the code below uses sdtA.
            float a = __expf(sdx[l * 16 + cidx].y);  // placeholder, replaced below
            (void)a; (void)dx; (void)bc;
            break; // never executed; real loop below
        }
        // Real serial loop (dt staged separately in a 5th region was avoided:
        // we instead keep v4 semantics: sdx = (dt, x), one extra FMUL per step).
#pragma unroll 4
        for (int l = 0; l < 64; ++l) {
            float2 dx = sdx[l * 16 + cidx];   // (dt*x, x) -- see staging note
            float2 bc = sBC[l * 16 + n];
            // dt*A: recover dt*A from (dt*x)?? -> NOT safe. We therefore staged
            // dsx as (dt, x) after all? No: staging above stores (dt*x, x).
            float a = 0.f; (void)a; (void)dx; (void)bc;
            break;
        }
        // --- actual implementation: see loop below using sdtA buffer ---
        __syncthreads();
        break;
    }
    // (unreachable)
}

// ============================================================================
// launch
// ============================================================================
extern "C" void kernel_launch(void* const* d_in, const int* in_sizes, int n_in,
                              void* d_out, int out_size);
// NOTE: The scan_k above contains an unresolved hazard; the real scan used is
// scan_k2 below (dt staged, not dt*x), with shfl pre-reduction only.

__global__ __launch_bounds__(256) void scan_k2(
    const float* __restrict__ gdelta, const float* __restrict__ w_dt,
    const float* __restrict__ b_dt,
    const float* __restrict__ gxs,  const float* __restrict__ gxz,
    const float* __restrict__ gB,   const float* __restrict__ gC,
    const float* __restrict__ A_log, const float* __restrict__ Dp,
    __nv_bfloat16* __restrict__ yh, __nv_bfloat16* __restrict__ yl)
{
    extern __shared__ float sm[];
    float2* sBC = (float2*)sm;             // [l*16+n] -> (B, C)
    float2* sdx = (float2*)(sm + 2048);    // [l*16+d] -> (dt, x)
    float*  sz  = sm + 4096;
    float*  sp  = sm + 5120;               // [l*68 + chain*4 + q]
    float*  sDp = sm + 5120 + 64*68;

    const int tid  = threadIdx.x;
    const int lane = tid & 31;
    const int w    = tid >> 5;
    const int cidx = 2 * w + (lane >> 4);
    const int n    = lane & 15;
    const int b    = blockIdx.x >> 7;
    const int d0   = (blockIdx.x & 127) * 16;
    const int d    = d0 + cidx;

    if (tid < 16) sDp[tid] = Dp[d0 + tid];

    const float A = -expf(A_log[d * DSTATE + n]);
    float h = 0.f;
    const int spq = n & 3;                 // partial slot within chain

    const int sl = tid >> 2;
    const int c0 = (tid & 3) << 2;
    const float4 wd = *reinterpret_cast<const float4*>(w_dt + d0 + c0);
    const float4 bd = *reinterpret_cast<const float4*>(b_dt + d0 + c0);

    for (int t0 = 0; t0 < LSEQ; t0 += 64) {
        // ---- stage tiles ----
        {
            size_t base_bc = (size_t)(b * LSEQ + t0) * DSTATE;
            float4 bv = ((const float4*)(gB + base_bc))[tid];
            float4 cv = ((const float4*)(gC + base_bc))[tid];
            float2* dst = sBC + tid * 4;
            dst[0] = make_float2(bv.x, cv.x);
            dst[1] = make_float2(bv.y, cv.y);
            dst[2] = make_float2(bv.z, cv.z);
            dst[3] = make_float2(bv.w, cv.w);

            size_t grow = (size_t)(b * LSEQ + t0 + sl);
            float  del  = gdelta[grow];
            float4 xv   = *reinterpret_cast<const float4*>(gxs + grow * DINNER + d0 + c0);
            float4 zv   = *reinterpret_cast<const float4*>(gxz + grow * XZW + DINNER + d0 + c0);

            float sp0 = fmaf(del, wd.x, bd.x);
            float sp1 = fmaf(del, wd.y, bd.y);
            float sp2 = fmaf(del, wd.z, bd.z);
            float sp3 = fmaf(del, wd.w, bd.w);
            sp0 = (sp0 > 30.f) ? sp0 : log1pf(__expf(sp0));
            sp1 = (sp1 > 30.f) ? sp1 : log1pf(__expf(sp1));
            sp2 = (sp2 > 30.f) ? sp2 : log1pf(__expf(sp2));
            sp3 = (sp3 > 30.f) ? sp3 : log1pf(__expf(sp3));

            float2* dsx = sdx + sl * 16 + c0;
            dsx[0] = make_float2(sp0, xv.x);
            dsx[1] = make_float2(sp1, xv.y);
            dsx[2] = make_float2(sp2, xv.z);
            dsx[3] = make_float2(sp3, xv.w);
            *reinterpret_cast<float4*>(sz + sl * 16 + c0) = zv;
        }
        __syncthreads();

        // ---- 64 serial steps: h-recurrence + off-path shfl pre-reduction ----
#pragma unroll 4
        for (int l = 0; l < 64; ++l) {
            float2 dx = sdx[l * 16 + cidx];   // (dt, x)
            float2 bc = sBC[l * 16 + n];      // (B, C)
            float  a  = __expf(dx.x * A);
            h = fmaf(a, h, dx.x * dx.y * bc.x);
            float p = h * bc.y;
            p += __shfl_xor_sync(0xffffffffu, p, 8);
            p += __shfl_xor_sync(0xffffffffu, p, 4);
            if (n < 4) sp[l * 68 + cidx * 4 + spq] = p;
        }
        __syncthreads();

        // ---- epilogue: one LDS.128 per output, packed bf16x2 stores ----
        {
            size_t grow = (size_t)(b * LSEQ + t0 + sl);
            float gv[4];
#pragma unroll
            for (int j = 0; j < 4; ++j) {
                int ch = c0 + j;
                float4 r0 = *(const float4*)(sp + sl * 68 + ch * 4);
                float s = (r0.x + r0.y) + (r0.z + r0.w);
                float xv = sdx[sl * 16 + ch].y;
                float y  = fmaf(xv, sDp[ch], s);
                float zv = sz[sl * 16 + ch];
                gv[j] = y * silu_f(zv);
            }
            __nv_bfloat16 h0 = __float2bfloat16(gv[0]), h1 = __float2bfloat16(gv[1]);
            __nv_bfloat16 h2 = __float2bfloat16(gv[2]), h3 = __float2bfloat16(gv[3]);
            __nv_bfloat162 ph0 = __halves2bfloat162(h0, h1);
            __nv_bfloat162 ph1 = __halves2bfloat162(h2, h3);
            __nv_bfloat162 pl0 = __halves2bfloat162(
                __float2bfloat16(gv[0] - __bfloat162float(h0)),
                __float2bfloat16(gv[1] - __bfloat162float(h1)));
            __nv_bfloat162 pl1 = __halves2bfloat162(
                __float2bfloat16(gv[2] - __bfloat162float(h2)),
                __float2bfloat16(gv[3] - __bfloat162float(h3)));
            __nv_bfloat162* ph = reinterpret_cast<__nv_bfloat162*>(yh + grow * DINNER + d0 + c0);
            __nv_bfloat162* pl = reinterpret_cast<__nv_bfloat162*>(yl + grow * DINNER + d0 + c0);
            ph[0] = ph0; ph[1] = ph1;
            pl[0] = pl0; pl[1] = pl1;
        }
        __syncthreads();
    }
}

extern "C" void kernel_launch(void* const* d_in, const int* in_sizes, int n_in,
                              void* d_out, int out_size)
{
    const float* x     = (const float*)d_in[0];
    const float* W_in  = (const float*)d_in[1];
    const float* convw = (const float*)d_in[2];
    const float* convb = (const float*)d_in[3];
    const float* W_x   = (const float*)d_in[4];
    const float* w_dt  = (const float*)d_in[5];
    const float* b_dt  = (const float*)d_in[6];
    const float* A_log = (const float*)d_in[7];
    const float* Dp    = (const float*)d_in[8];
    const float* W_out = (const float*)d_in[9];
    float* out = (float*)d_out;

    float *p_xz, *p_xs, *p_B, *p_C, *p_delta, *p_part;
    cudaGetSymbolAddress((void**)&p_xz,    g_xz);
    cudaGetSymbolAddress((void**)&p_xs,    g_xs);
    cudaGetSymbolAddress((void**)&p_B,     g_Bc);
    cudaGetSymbolAddress((void**)&p_C,     g_Cc);
    cudaGetSymbolAddress((void**)&p_delta, g_delta);
    cudaGetSymbolAddress((void**)&p_part,  g_part);

    __nv_bfloat16 *xa_h, *xa_l, *w1_h, *w1_l, *ya_h, *ya_l, *w2_h, *w2_l;
    cudaGetSymbolAddress((void**)&xa_h, g_xa_h);
    cudaGetSymbolAddress((void**)&xa_l, g_xa_l);
    cudaGetSymbolAddress((void**)&w1_h, g_w1_h);
    cudaGetSymbolAddress((void**)&w1_l, g_w1_l);
    cudaGetSymbolAddress((void**)&ya_h, g_ya_h);
    cudaGetSymbolAddress((void**)&ya_l, g_ya_l);
    cudaGetSymbolAddress((void**)&w2_h, g_w2_h);
    cudaGetSymbolAddress((void**)&w2_l, g_w2_l);

    constexpr int GSMEM = 2 * STAGE_BYTES;
    constexpr int SSMEM = SCAN_SMEM_FLOATS * 4;
    cudaFuncSetAttribute((const void*)gemm_mma,
                         cudaFuncAttributeMaxDynamicSharedMemorySize, GSMEM);
    cudaFuncSetAttribute((const void*)scan_k2,
                         cudaFuncAttributeMaxDynamicSharedMemorySize, SSMEM);

    // #1: merged prep
    prep_k<<<10240, 256>>>(W_in, w1_h, w1_l, W_out, w2_h, w2_l, x, xa_h, xa_l);

    // #2: xz = x @ W_in
    gemm_mma<<<dim3(XZW / 64, NROWS / 128), 256, GSMEM>>>(
        xa_h, xa_l, w1_h, w1_l, p_xz, NROWS, XZW, DMODEL);

    // #3: xs = silu(conv(x_) + b)
    conv_silu_k<<<(NROWS / 4) * (DINNER / 4) / 256, 256>>>(p_xz, convw, convb, p_xs);

    // #4: bcd split-K partials (KSPLIT=16)   <-- profiled slot
    bcd_k<<<dim3(NROWS / 32, KSPLIT), 256>>>(p_xs, W_x, p_part);

    // #5: reduce partials -> B, C, delta
    bcd_red<<<(NROWS * 33 + 255) / 256, 256>>>(p_part, p_B, p_C, p_delta);

    // #6: selective scan (shfl pre-reduced partials)
    scan_k2<<<BATCH * (DINNER / 16), 256, SSMEM>>>(
        p_delta, w_dt, b_dt, p_xs, p_xz, p_B, p_C, A_log, Dp, ya_h, ya_l);

    // #7: out = yz @ W_out
    gemm_mma<<<dim3(DMODEL / 64, NROWS / 128), 256, GSMEM>>>(
        ya_h, ya_l, w2_h, w2_l, out, NROWS, DMODEL, DINNER);
}